// round 14
// baseline (speedup 1.0000x reference)
#include <cuda_runtime.h>
#include <cuda_bf16.h>
#include <math.h>
#include <cstdint>

#define BATCH 8
#define SEQ   1024
#define DIMC  768
#define NH    12
#define HD    64
#define M_TOT (BATCH*SEQ)     /* 8192 */
#define QK_SCALE 0.125f
#define BH    (BATCH*NH)      /* 96 */

typedef __nv_bfloat16 bf16;

/* ---------------- scratch (no cudaMalloc allowed) ---------------- */
__device__ __align__(16) int8_t g_x1[M_TOT*DIMC],  g_x2[M_TOT*DIMC];
__device__ __align__(16) int8_t g_wq1[3*DIMC*DIMC], g_wq2[3*DIMC*DIMC];
__device__ __align__(16) int8_t g_wp1[DIMC*DIMC],  g_wp2[DIMC*DIMC];
__device__ __align__(16) int8_t g_ao1[M_TOT*DIMC], g_ao2[M_TOT*DIMC];
__device__ float g_sx[M_TOT], g_swq[3*DIMC], g_swp[DIMC], g_sao[M_TOT];
__device__ float g_ao[M_TOT*DIMC];                       /* flash out fp32 */
__device__ bf16 g_qh[BH*SEQ*HD], g_ql[BH*SEQ*HD];
__device__ bf16 g_kh[BH*SEQ*HD], g_kl[BH*SEQ*HD];
__device__ bf16 g_vh[BH*SEQ*HD], g_vl[BH*SEQ*HD];
__device__ int   g_kidx[BATCH*SEQ];
__device__ float g_cmask[BATCH*SEQ];
__device__ int   g_kcnt[BATCH];

__device__ __forceinline__ uint32_t smem_to_u32(const void* p) {
    uint32_t a;
    asm("{ .reg .u64 t; cvta.to.shared.u64 t, %1; cvt.u32.u64 %0, t; }" : "=r"(a) : "l"(p));
    return a;
}

/* ---------------- baseline-PTX tensor / async ops ---------------- */
__device__ __forceinline__ void ldsm_x4(uint32_t& a0, uint32_t& a1, uint32_t& a2,
                                        uint32_t& a3, uint32_t addr) {
    asm volatile("ldmatrix.sync.aligned.m8n8.x4.shared.b16 {%0,%1,%2,%3}, [%4];"
                 : "=r"(a0), "=r"(a1), "=r"(a2), "=r"(a3) : "r"(addr));
}
__device__ __forceinline__ void ldsm_x4_t(uint32_t& a0, uint32_t& a1, uint32_t& a2,
                                          uint32_t& a3, uint32_t addr) {
    asm volatile("ldmatrix.sync.aligned.m8n8.x4.trans.shared.b16 {%0,%1,%2,%3}, [%4];"
                 : "=r"(a0), "=r"(a1), "=r"(a2), "=r"(a3) : "r"(addr));
}
__device__ __forceinline__ void mma_bf16(float (&c)[4], const uint32_t (&a)[4],
                                         const uint32_t (&b)[2]) {
    asm volatile("mma.sync.aligned.m16n8k16.row.col.f32.bf16.bf16.f32 "
                 "{%0,%1,%2,%3}, {%4,%5,%6,%7}, {%8,%9}, {%0,%1,%2,%3};"
                 : "+f"(c[0]), "+f"(c[1]), "+f"(c[2]), "+f"(c[3])
                 : "r"(a[0]), "r"(a[1]), "r"(a[2]), "r"(a[3]), "r"(b[0]), "r"(b[1]));
}
__device__ __forceinline__ void mma_s8(int (&c)[4], const uint32_t (&a)[4],
                                       const uint32_t (&b)[2]) {
    asm volatile("mma.sync.aligned.m16n8k32.row.col.s32.s8.s8.s32 "
                 "{%0,%1,%2,%3}, {%4,%5,%6,%7}, {%8,%9}, {%0,%1,%2,%3};"
                 : "+r"(c[0]), "+r"(c[1]), "+r"(c[2]), "+r"(c[3])
                 : "r"(a[0]), "r"(a[1]), "r"(a[2]), "r"(a[3]), "r"(b[0]), "r"(b[1]));
}
#define CP16(dst, src) \
    asm volatile("cp.async.cg.shared.global [%0], [%1], 16;" :: "r"(dst), "l"(src))
#define CP_COMMIT() asm volatile("cp.async.commit_group;" ::: "memory")
#define CP_WAIT1()  asm volatile("cp.async.wait_group 1;" ::: "memory")
#define CP_WAIT0()  asm volatile("cp.async.wait_group 0;" ::: "memory")

__device__ __forceinline__ void split2(float a, float b, uint32_t& hi, uint32_t& lo) {
    bf16 ha = __float2bfloat16(a), hb = __float2bfloat16(b);
    bf16 la = __float2bfloat16(a - __bfloat162float(ha));
    bf16 lb = __float2bfloat16(b - __bfloat162float(hb));
    hi = ((uint32_t)__bfloat16_as_ushort(hb) << 16) | __bfloat16_as_ushort(ha);
    lo = ((uint32_t)__bfloat16_as_ushort(lb) << 16) | __bfloat16_as_ushort(la);
}

/* ---------------- quantization: fp32 row -> 2 int8 slices + scale ---------- */
__device__ __forceinline__ void quant_row(const float* __restrict__ p, size_t rbase,
                                          int8_t* __restrict__ d1,
                                          int8_t* __restrict__ d2,
                                          float* __restrict__ sc, int r) {
    __shared__ float wmax[4];
    const int tid = threadIdx.x, lane = tid & 31, wid = tid >> 5;
    float mx = 0.f;
    for (int j = tid; j < DIMC; j += 128) mx = fmaxf(mx, fabsf(p[rbase + j]));
#pragma unroll
    for (int off = 16; off >= 1; off >>= 1)
        mx = fmaxf(mx, __shfl_xor_sync(0xffffffffu, mx, off));
    if (lane == 0) wmax[wid] = mx;
    __syncthreads();
    mx = fmaxf(fmaxf(wmax[0], wmax[1]), fmaxf(wmax[2], wmax[3]));
    float s = fmaxf(mx, 1e-20f) * (1.0f/127.0f);
    float inv = 1.0f / s;
    for (int j = tid; j < DIMC; j += 128) {
        float v = p[rbase + j];
        int a1 = __float2int_rn(v * inv);
        float res = v - (float)a1 * s;
        int a2 = __float2int_rn(res * inv * 128.0f);
        d1[rbase + j] = (int8_t)a1;
        d2[rbase + j] = (int8_t)a2;
    }
    if (tid == 0) sc[r] = s;
}

__global__ void quant_inputs(const float* __restrict__ x,
                             const float* __restrict__ wq,
                             const float* __restrict__ wp) {
    int row = blockIdx.x;
    if (row < M_TOT)
        quant_row(x, (size_t)row * DIMC, g_x1, g_x2, g_sx, row);
    else if (row < M_TOT + 3*DIMC) {
        int r = row - M_TOT;
        quant_row(wq, (size_t)r * DIMC, g_wq1, g_wq2, g_swq, r);
    } else {
        int r = row - M_TOT - 3*DIMC;
        quant_row(wp, (size_t)r * DIMC, g_wp1, g_wp2, g_swp, r);
    }
}
__global__ void quant_ao() {
    int row = blockIdx.x;
    quant_row(g_ao, (size_t)row * DIMC, g_ao1, g_ao2, g_sao, row);
}

/* single block: sniff mask dtype, compact unmasked key indices per batch */
__global__ void mask_prep_kernel(const unsigned char* __restrict__ m) {
    __shared__ int sc[SEQ];
    __shared__ int s_any;
    const int tid = threadIdx.x;
    if (tid == 0) s_any = 0;
    __syncthreads();
    int loc = 0;
    for (int i = tid; i < BATCH*SEQ; i += SEQ)
        if ((i & 3) && m[i]) loc = 1;
    if (loc) s_any = 1;
    __syncthreads();
    const bool mbyte = (s_any != 0);
    const int* mi = (const int*)m;
    for (int b = 0; b < BATCH; b++) {
        bool masked = mbyte ? (m[b*SEQ + tid] != 0) : (mi[b*SEQ + tid] != 0);
        int flag = masked ? 0 : 1;
        sc[tid] = flag;
        __syncthreads();
        for (int off = 1; off < SEQ; off <<= 1) {
            int v = sc[tid];
            if (tid >= off) v += sc[tid - off];
            __syncthreads();
            sc[tid] = v;
            __syncthreads();
        }
        int incl = sc[tid];
        int cnt  = sc[SEQ-1];
        if (flag) g_kidx[b*SEQ + incl - 1] = tid;
        if (tid >= cnt) g_kidx[b*SEQ + tid] = 0;
        g_cmask[b*SEQ + tid] = (tid < cnt) ? 0.f : -1e30f;
        if (tid == 0) g_kcnt[b] = cnt;
        __syncthreads();
    }
}

/* ======================================================================
   int8 dual-slice GEMM: C = sA.sB.(a1b1 + (a1b2 + a2b1)/128).
   CTA 128x128, 8 warps (2x4), warp 64x32. KC=64 int8, k32 IMMA.
   3-stage cp.async pipeline, single barrier per chunk. 1 CTA/SM.
   MODE 0: QKV -> bf16 hi/lo q/k/v planes. MODE 1: proj -> fp32 out.
   ====================================================================== */
#define KCB   64
#define NCHB  (768/KCB)            /* 12 */
#define GSB   80                   /* bytes per smem row (conflict-free) */
#define PLANE_I (128*GSB)          /* 10240 B */
#define STAGE_I (4*PLANE_I)        /* 40960 B */
#define NSTG  3
#define GEMM_SMEM_I (NSTG*STAGE_I) /* 122880 B */

template<int MODE>
__global__ void __launch_bounds__(256, 1) gemm_i8(
    const int8_t* __restrict__ A1g, const int8_t* __restrict__ A2g,
    const int8_t* __restrict__ B1g, const int8_t* __restrict__ B2g,
    const float* __restrict__ sAv, const float* __restrict__ sBv,
    const float* __restrict__ bias0, const float* __restrict__ bias1,
    float* __restrict__ Cout)
{
    extern __shared__ __align__(16) char smb[];
    const uint32_t sb = smem_to_u32(smb);

    const int tid = threadIdx.x;
    const int lane = tid & 31;
    const int wid = tid >> 5;
    const int wm = wid >> 2, wn = wid & 3;
    const int bm = blockIdx.y * 128, bn = blockIdx.x * 128;

    const int a_row = lane & 15;
    const int a_cb16 = (lane >> 4) << 4;   /* 0 or 16 byte column split */

    int acc1[4][4][4], acc2[4][4][4];
#pragma unroll
    for (int i = 0; i < 4; i++)
#pragma unroll
        for (int j = 0; j < 4; j++)
#pragma unroll
            for (int t = 0; t < 4; t++) { acc1[i][j][t] = 0; acc2[i][j][t] = 0; }

    /* one stage: 4 planes x 512 16B-slots (128 rows x 64 B) = 8/thread */
    auto issue = [&](int kc) {
        const int k0 = kc * KCB;
        const uint32_t st = sb + (uint32_t)((kc % NSTG) * STAGE_I);
#pragma unroll
        for (int u = 0; u < 8; u++) {
            int idx = tid + u * 256;
            int plane = idx >> 9;
            int rem = idx & 511;
            int row = rem >> 2;
            int c16 = (rem & 3) << 4;
            const int8_t* gp = (plane == 0) ? A1g : (plane == 1) ? A2g
                               : (plane == 2) ? B1g : B2g;
            int rb = (plane < 2) ? bm : bn;
            uint32_t d = st + (uint32_t)(plane * PLANE_I) + (uint32_t)(row * GSB + c16);
            CP16(d, gp + (size_t)(rb + row) * 768 + k0 + c16);
        }
        CP_COMMIT();
    };

    issue(0); issue(1);
    for (int kc = 0; kc < NCHB; kc++) {
        if (kc + 1 < NCHB) CP_WAIT1(); else CP_WAIT0();
        __syncthreads();
        if (kc + 2 < NCHB) issue(kc + 2);

        const uint32_t st = sb + (uint32_t)((kc % NSTG) * STAGE_I);
        const uint32_t pA1 = st, pA2 = st + PLANE_I;
        const uint32_t pB1 = st + 2*PLANE_I, pB2 = st + 3*PLANE_I;
#pragma unroll
        for (int ks = 0; ks < 2; ks++) {
            const int kb = ks * 32;
            uint32_t af[4][4], b1f[4][2], b2f[4][2];
#pragma unroll
            for (int mf = 0; mf < 4; mf++) {
                uint32_t ad = pA1 + (uint32_t)((wm*64 + mf*16 + a_row) * GSB + kb + a_cb16);
                ldsm_x4(af[mf][0], af[mf][1], af[mf][2], af[mf][3], ad);
            }
#pragma unroll
            for (int np = 0; np < 2; np++) {
                uint32_t bd = pB1 + (uint32_t)((wn*32 + np*16 + a_row) * GSB + kb + a_cb16);
                uint32_t r0, r1, r2, r3;
                ldsm_x4(r0, r1, r2, r3, bd);
                b1f[2*np][0] = r0; b1f[2*np][1] = r2;
                b1f[2*np+1][0] = r1; b1f[2*np+1][1] = r3;
            }
            /* P11: a1*b1 -> acc1 */
#pragma unroll
            for (int mf = 0; mf < 4; mf++)
#pragma unroll
                for (int nf = 0; nf < 4; nf++)
                    mma_s8(acc1[mf][nf], af[mf], b1f[nf]);
#pragma unroll
            for (int np = 0; np < 2; np++) {
                uint32_t bd = pB2 + (uint32_t)((wn*32 + np*16 + a_row) * GSB + kb + a_cb16);
                uint32_t r0, r1, r2, r3;
                ldsm_x4(r0, r1, r2, r3, bd);
                b2f[2*np][0] = r0; b2f[2*np][1] = r2;
                b2f[2*np+1][0] = r1; b2f[2*np+1][1] = r3;
            }
            /* P12: a1*b2 -> acc2 */
#pragma unroll
            for (int mf = 0; mf < 4; mf++)
#pragma unroll
                for (int nf = 0; nf < 4; nf++)
                    mma_s8(acc2[mf][nf], af[mf], b2f[nf]);
            /* P21: a2*b1 -> acc2 (reuse af regs) */
#pragma unroll
            for (int mf = 0; mf < 4; mf++) {
                uint32_t ad = pA2 + (uint32_t)((wm*64 + mf*16 + a_row) * GSB + kb + a_cb16);
                ldsm_x4(af[mf][0], af[mf][1], af[mf][2], af[mf][3], ad);
            }
#pragma unroll
            for (int mf = 0; mf < 4; mf++)
#pragma unroll
                for (int nf = 0; nf < 4; nf++)
                    mma_s8(acc2[mf][nf], af[mf], b1f[nf]);
        }
    }

    const int gr = lane >> 2;
    const int gc = (lane & 3) << 1;
#pragma unroll
    for (int mf = 0; mf < 4; mf++) {
#pragma unroll
        for (int nf = 0; nf < 4; nf++) {
            int n0 = bn + wn*32 + nf*8 + gc;
            float sb0 = sBv[n0], sb1 = sBv[n0+1];
#pragma unroll
            for (int half = 0; half < 2; half++) {
                int m = bm + wm*64 + mf*16 + gr + half*8;
                float sa = sAv[m];
                float v0 = sa * sb0 * ((float)acc1[mf][nf][half*2+0]
                                       + (float)acc2[mf][nf][half*2+0] * 0.0078125f);
                float v1 = sa * sb1 * ((float)acc1[mf][nf][half*2+1]
                                       + (float)acc2[mf][nf][half*2+1] * 0.0078125f);
                if (MODE == 1) {
                    float2 o = make_float2(v0 + bias0[n0], v1 + bias0[n0+1]);
                    *(float2*)(Cout + (size_t)m * 768 + n0) = o;
                } else {
                    int which = n0 / 768;
                    int nn = n0 % 768;
                    int h = nn >> 6, d0 = nn & 63;
                    int b = m >> 10, tok = m & 1023;
                    if (which == 0) {
                        v0 = (v0 + bias0[nn])   * QK_SCALE;
                        v1 = (v1 + bias0[nn+1]) * QK_SCALE;
                    } else if (which == 2) {
                        v0 += bias1[nn];
                        v1 += bias1[nn+1];
                    }
                    uint32_t hp, lp;
                    split2(v0, v1, hp, lp);
                    size_t off = ((size_t)((b*NH + h)*SEQ + tok)) * HD + d0;
                    bf16* ph = (which == 0) ? g_qh : ((which == 1) ? g_kh : g_vh);
                    bf16* pl = (which == 0) ? g_ql : ((which == 1) ? g_kl : g_vl);
                    *(uint32_t*)(ph + off) = hp;
                    *(uint32_t*)(pl + off) = lp;
                }
            }
        }
    }
}

/* ======================================================================
   flash attention over compacted keys (bf16 split, proven R13 version).
   Epilogue now writes fp32 g_ao.
   ====================================================================== */
#define FS     72
#define FPLANE_B (64*FS*2)
#define FSTAGE_B (4*FPLANE_B)
#define FLASH_SMEM (2*FSTAGE_B)

__global__ void __launch_bounds__(128, 3) flash_mma()
{
    extern __shared__ __align__(16) bf16 fsm[];
    const uint32_t sb = smem_to_u32(fsm);

    const int tid = threadIdx.x;
    const int lane = tid & 31;
    const int wid = tid >> 5;
    const int bh = blockIdx.y;
    const int qt = blockIdx.x;
    const int b = bh / NH, h = bh % NH;

    const size_t qbase = ((size_t)bh*SEQ + qt*64) * HD;
    const size_t kvbase = (size_t)bh*SEQ*HD;
    const int cnt = g_kcnt[b];
    const int ntiles = (cnt + 63) >> 6;
    const int* kidx = g_kidx + b*SEQ;

#pragma unroll
    for (int u = 0; u < 8; u++) {
        int idx = tid + u * 128;
        int plane = idx >> 9;
        int rem = idx & 511;
        int row = rem >> 3;
        int c8 = (rem & 7) << 3;
        const bf16* src = plane ? g_ql : g_qh;
        *(uint4*)(fsm + plane*(64*FS) + row*FS + c8) =
            *(const uint4*)(src + qbase + (size_t)row*64 + c8);
    }
    __syncthreads();

    uint32_t qh[4][4], ql[4][4];
    {
        int row = wid*16 + (lane & 15);
        int cb = (lane >> 4) << 3;
#pragma unroll
        for (int ks = 0; ks < 4; ks++) {
            uint32_t off = (uint32_t)((row*FS + ks*16 + cb) * 2);
            ldsm_x4(qh[ks][0], qh[ks][1], qh[ks][2], qh[ks][3], sb + off);
            ldsm_x4(ql[ks][0], ql[ks][1], ql[ks][2], ql[ks][3],
                    sb + (uint32_t)FPLANE_B + off);
        }
    }
    __syncthreads();

    auto issue_kv = [&](int j) {
        const uint32_t st = sb + (uint32_t)((j & 1) * FSTAGE_B);
#pragma unroll
        for (int u = 0; u < 16; u++) {
            int idx = tid + u * 128;
            int plane = idx >> 9;
            int rem = idx & 511;
            int row = rem >> 3;
            int c8 = (rem & 7) << 3;
            int src_row = kidx[j*64 + row];
            const bf16* gp = (plane == 0) ? g_kh : (plane == 1) ? g_kl
                             : (plane == 2) ? g_vh : g_vl;
            uint32_t d = st + (uint32_t)(plane * FPLANE_B) + (uint32_t)((row*FS + c8) * 2);
            CP16(d, gp + kvbase + (size_t)src_row*64 + c8);
        }
        CP_COMMIT();
    };

    float o[8][4];
#pragma unroll
    for (int i = 0; i < 8; i++)
#pragma unroll
        for (int t = 0; t < 4; t++) o[i][t] = 0.f;
    float m0 = -1e30f, m1 = -1e30f, l0 = 0.f, l1 = 0.f;

    const int gr = lane >> 2;
    const int gc = (lane & 3) << 1;
    const int frow = lane & 15;
    const int fcb = (lane >> 4) << 3;

    issue_kv(0);
    for (int kt = 0; kt < ntiles; kt++) {
        float2 mk[8];
#pragma unroll
        for (int nf = 0; nf < 8; nf++)
            mk[nf] = *(const float2*)(g_cmask + b*SEQ + kt*64 + nf*8 + gc);

        if (kt + 1 < ntiles) { issue_kv(kt + 1); CP_WAIT1(); }
        else                 { CP_WAIT0(); }
        __syncthreads();

        const uint32_t st = sb + (uint32_t)((kt & 1) * FSTAGE_B);
        const uint32_t pKh = st, pKl = st + FPLANE_B;
        const uint32_t pVh = st + 2*FPLANE_B, pVl = st + 3*FPLANE_B;

        float s4[8][4];
#pragma unroll
        for (int i = 0; i < 8; i++)
#pragma unroll
            for (int t = 0; t < 4; t++) s4[i][t] = 0.f;

#pragma unroll
        for (int ks = 0; ks < 4; ks++) {
            uint32_t kbh[8][2], kbl[8][2];
#pragma unroll
            for (int np = 0; np < 4; np++) {
                uint32_t off = (uint32_t)(((np*16 + frow)*FS + ks*16 + fcb) * 2);
                uint32_t r0, r1, r2, r3;
                ldsm_x4(r0, r1, r2, r3, pKh + off);
                kbh[2*np][0] = r0; kbh[2*np][1] = r2;
                kbh[2*np+1][0] = r1; kbh[2*np+1][1] = r3;
                ldsm_x4(r0, r1, r2, r3, pKl + off);
                kbl[2*np][0] = r0; kbl[2*np][1] = r2;
                kbl[2*np+1][0] = r1; kbl[2*np+1][1] = r3;
            }
#pragma unroll
            for (int nf = 0; nf < 8; nf++) mma_bf16(s4[nf], qh[ks], kbh[nf]);
#pragma unroll
            for (int nf = 0; nf < 8; nf++) mma_bf16(s4[nf], ql[ks], kbh[nf]);
#pragma unroll
            for (int nf = 0; nf < 8; nf++) mma_bf16(s4[nf], qh[ks], kbl[nf]);
        }

        float tm0 = -1e30f, tm1 = -1e30f;
#pragma unroll
        for (int nf = 0; nf < 8; nf++) {
            s4[nf][0] += mk[nf].x; s4[nf][1] += mk[nf].y;
            s4[nf][2] += mk[nf].x; s4[nf][3] += mk[nf].y;
            tm0 = fmaxf(tm0, fmaxf(s4[nf][0], s4[nf][1]));
            tm1 = fmaxf(tm1, fmaxf(s4[nf][2], s4[nf][3]));
        }
        tm0 = fmaxf(tm0, __shfl_xor_sync(0xffffffffu, tm0, 1));
        tm0 = fmaxf(tm0, __shfl_xor_sync(0xffffffffu, tm0, 2));
        tm1 = fmaxf(tm1, __shfl_xor_sync(0xffffffffu, tm1, 1));
        tm1 = fmaxf(tm1, __shfl_xor_sync(0xffffffffu, tm1, 2));
        float mn0 = fmaxf(m0, tm0), mn1 = fmaxf(m1, tm1);
        float al0 = __expf(m0 - mn0), al1 = __expf(m1 - mn1);
        m0 = mn0; m1 = mn1;
        float ls0 = 0.f, ls1 = 0.f;
#pragma unroll
        for (int nf = 0; nf < 8; nf++) {
            s4[nf][0] = __expf(s4[nf][0] - mn0);
            s4[nf][1] = __expf(s4[nf][1] - mn0);
            s4[nf][2] = __expf(s4[nf][2] - mn1);
            s4[nf][3] = __expf(s4[nf][3] - mn1);
            ls0 += s4[nf][0] + s4[nf][1];
            ls1 += s4[nf][2] + s4[nf][3];
        }
        ls0 += __shfl_xor_sync(0xffffffffu, ls0, 1);
        ls0 += __shfl_xor_sync(0xffffffffu, ls0, 2);
        ls1 += __shfl_xor_sync(0xffffffffu, ls1, 1);
        ls1 += __shfl_xor_sync(0xffffffffu, ls1, 2);
        l0 = l0 * al0 + ls0;
        l1 = l1 * al1 + ls1;
#pragma unroll
        for (int nf = 0; nf < 8; nf++) {
            o[nf][0] *= al0; o[nf][1] *= al0;
            o[nf][2] *= al1; o[nf][3] *= al1;
        }

#pragma unroll
        for (int ksv = 0; ksv < 4; ksv++) {
            uint32_t ph[4], pl[4];
            split2(s4[2*ksv][0],   s4[2*ksv][1],   ph[0], pl[0]);
            split2(s4[2*ksv][2],   s4[2*ksv][3],   ph[1], pl[1]);
            split2(s4[2*ksv+1][0], s4[2*ksv+1][1], ph[2], pl[2]);
            split2(s4[2*ksv+1][2], s4[2*ksv+1][3], ph[3], pl[3]);
            uint32_t vhf[8][2], vlf[8][2];
#pragma unroll
            for (int np = 0; np < 4; np++) {
                uint32_t off = (uint32_t)(((ksv*16 + frow)*FS + np*16 + fcb) * 2);
                uint32_t r0, r1, r2, r3;
                ldsm_x4_t(r0, r1, r2, r3, pVh + off);
                vhf[2*np][0] = r0; vhf[2*np][1] = r1;
                vhf[2*np+1][0] = r2; vhf[2*np+1][1] = r3;
                ldsm_x4_t(r0, r1, r2, r3, pVl + off);
                vlf[2*np][0] = r0; vlf[2*np][1] = r1;
                vlf[2*np+1][0] = r2; vlf[2*np+1][1] = r3;
            }
#pragma unroll
            for (int nf = 0; nf < 8; nf++) mma_bf16(o[nf], ph, vhf[nf]);
#pragma unroll
            for (int nf = 0; nf < 8; nf++) mma_bf16(o[nf], ph, vlf[nf]);
#pragma unroll
            for (int nf = 0; nf < 8; nf++) mma_bf16(o[nf], pl, vhf[nf]);
        }
        __syncthreads();
    }

    float inv0 = 1.f / l0, inv1 = 1.f / l1;
    int tok0 = qt*64 + wid*16 + gr;
    size_t r0g = ((size_t)(b*SEQ + tok0)) * DIMC + h*HD;
    size_t r1g = r0g + 8*DIMC;
#pragma unroll
    for (int nf = 0; nf < 8; nf++) {
        int d = nf*8 + gc;
        *(float2*)(g_ao + r0g + d) = make_float2(o[nf][0]*inv0, o[nf][1]*inv0);
        *(float2*)(g_ao + r1g + d) = make_float2(o[nf][2]*inv1, o[nf][3]*inv1);
    }
}

/* ---------------- launcher ---------------- */
extern "C" void kernel_launch(void* const* d_in, const int* in_sizes, int n_in,
                              void* d_out, int out_size)
{
    const float* x           = (const float*)d_in[0];
    const unsigned char* msk = (const unsigned char*)d_in[1];
    const float* qkv_w       = (const float*)d_in[2];
    const float* q_bias      = (const float*)d_in[3];
    const float* v_bias      = (const float*)d_in[4];
    const float* proj_w      = (const float*)d_in[5];
    const float* proj_b      = (const float*)d_in[6];
    float* out               = (float*)d_out;

    (void)in_sizes; (void)n_in; (void)out_size;

    cudaFuncSetAttribute(gemm_i8<0>, cudaFuncAttributeMaxDynamicSharedMemorySize, GEMM_SMEM_I);
    cudaFuncSetAttribute(gemm_i8<1>, cudaFuncAttributeMaxDynamicSharedMemorySize, GEMM_SMEM_I);
    cudaFuncSetAttribute(flash_mma, cudaFuncAttributeMaxDynamicSharedMemorySize, FLASH_SMEM);

    mask_prep_kernel<<<1, 1024>>>(msk);
    quant_inputs<<<M_TOT + 3*DIMC + DIMC, 128>>>(x, qkv_w, proj_w);

    int8_t *x1, *x2, *wq1, *wq2, *wp1, *wp2, *ao1, *ao2;
    float *sx, *swq, *swp, *sao;
    cudaGetSymbolAddress((void**)&x1,  g_x1);  cudaGetSymbolAddress((void**)&x2,  g_x2);
    cudaGetSymbolAddress((void**)&wq1, g_wq1); cudaGetSymbolAddress((void**)&wq2, g_wq2);
    cudaGetSymbolAddress((void**)&wp1, g_wp1); cudaGetSymbolAddress((void**)&wp2, g_wp2);
    cudaGetSymbolAddress((void**)&ao1, g_ao1); cudaGetSymbolAddress((void**)&ao2, g_ao2);
    cudaGetSymbolAddress((void**)&sx,  g_sx);  cudaGetSymbolAddress((void**)&swq, g_swq);
    cudaGetSymbolAddress((void**)&swp, g_swp); cudaGetSymbolAddress((void**)&sao, g_sao);

    gemm_i8<0><<<dim3(2304/128, M_TOT/128), 256, GEMM_SMEM_I>>>(
        x1, x2, wq1, wq2, sx, swq, q_bias, v_bias, nullptr);

    flash_mma<<<dim3(SEQ/64, BH), 128, FLASH_SMEM>>>();

    quant_ao<<<M_TOT, 128>>>();

    gemm_i8<1><<<dim3(768/128, M_TOT/128), 256, GEMM_SMEM_I>>>(
        ao1, ao2, wp1, wp2, sao, swp, proj_b, nullptr, out);
}

// round 17
// speedup vs baseline: 2.3917x; 2.3917x over previous
#include <cuda_runtime.h>
#include <cuda_bf16.h>
#include <cuda_fp16.h>
#include <math.h>
#include <cstdint>

#define BATCH 8
#define SEQ   1024
#define DIMC  768
#define NH    12
#define HD    64
#define M_TOT (BATCH*SEQ)     /* 8192 */
#define QK_SCALE 0.125f
#define BH    (BATCH*NH)      /* 96 */

typedef __nv_bfloat16 bf16;

/* ---------------- scratch (no cudaMalloc allowed) ---------------- */
__device__ __half g_xh[M_TOT*DIMC],  g_xl[M_TOT*DIMC];      /* x fp16 hi/lo  */
__device__ __half g_wqh[3*DIMC*DIMC];                       /* qkv_w fp16 hi */
__device__ __half g_wph[DIMC*DIMC];                         /* proj_w fp16 hi*/
__device__ __half g_aoh[M_TOT*DIMC], g_aol[M_TOT*DIMC];     /* attn out      */
__device__ bf16 g_qh[BH*SEQ*HD], g_ql[BH*SEQ*HD];           /* bf16 (flash)  */
__device__ bf16 g_kh[BH*SEQ*HD], g_kl[BH*SEQ*HD];
__device__ bf16 g_vh[BH*SEQ*HD], g_vl[BH*SEQ*HD];
__device__ int   g_kidx[BATCH*SEQ];
__device__ float g_cmask[BATCH*SEQ];
__device__ int   g_kcnt[BATCH];

__device__ __forceinline__ uint32_t smem_to_u32(const void* p) {
    uint32_t a;
    asm("{ .reg .u64 t; cvta.to.shared.u64 t, %1; cvt.u32.u64 %0, t; }" : "=r"(a) : "l"(p));
    return a;
}

/* ---------------- baseline-PTX tensor / async ops ---------------- */
__device__ __forceinline__ void ldsm_x4(uint32_t& a0, uint32_t& a1, uint32_t& a2,
                                        uint32_t& a3, uint32_t addr) {
    asm volatile("ldmatrix.sync.aligned.m8n8.x4.shared.b16 {%0,%1,%2,%3}, [%4];"
                 : "=r"(a0), "=r"(a1), "=r"(a2), "=r"(a3) : "r"(addr));
}
__device__ __forceinline__ void ldsm_x4_t(uint32_t& a0, uint32_t& a1, uint32_t& a2,
                                          uint32_t& a3, uint32_t addr) {
    asm volatile("ldmatrix.sync.aligned.m8n8.x4.trans.shared.b16 {%0,%1,%2,%3}, [%4];"
                 : "=r"(a0), "=r"(a1), "=r"(a2), "=r"(a3) : "r"(addr));
}
__device__ __forceinline__ void mma_bf16(float (&c)[4], const uint32_t (&a)[4],
                                         const uint32_t (&b)[2]) {
    asm volatile("mma.sync.aligned.m16n8k16.row.col.f32.bf16.bf16.f32 "
                 "{%0,%1,%2,%3}, {%4,%5,%6,%7}, {%8,%9}, {%0,%1,%2,%3};"
                 : "+f"(c[0]), "+f"(c[1]), "+f"(c[2]), "+f"(c[3])
                 : "r"(a[0]), "r"(a[1]), "r"(a[2]), "r"(a[3]), "r"(b[0]), "r"(b[1]));
}
__device__ __forceinline__ void mma_f16(float (&c)[4], const uint32_t (&a)[4],
                                        const uint32_t (&b)[2]) {
    asm volatile("mma.sync.aligned.m16n8k16.row.col.f32.f16.f16.f32 "
                 "{%0,%1,%2,%3}, {%4,%5,%6,%7}, {%8,%9}, {%0,%1,%2,%3};"
                 : "+f"(c[0]), "+f"(c[1]), "+f"(c[2]), "+f"(c[3])
                 : "r"(a[0]), "r"(a[1]), "r"(a[2]), "r"(a[3]), "r"(b[0]), "r"(b[1]));
}
#define CP16(dst, src) \
    asm volatile("cp.async.cg.shared.global [%0], [%1], 16;" :: "r"(dst), "l"(src))
#define CP_COMMIT() asm volatile("cp.async.commit_group;" ::: "memory")
#define CP_WAIT1()  asm volatile("cp.async.wait_group 1;" ::: "memory")
#define CP_WAIT0()  asm volatile("cp.async.wait_group 0;" ::: "memory")

/* bf16 split (flash q/k/v planes) */
__device__ __forceinline__ void split2(float a, float b, uint32_t& hi, uint32_t& lo) {
    bf16 ha = __float2bfloat16(a), hb = __float2bfloat16(b);
    bf16 la = __float2bfloat16(a - __bfloat162float(ha));
    bf16 lb = __float2bfloat16(b - __bfloat162float(hb));
    hi = ((uint32_t)__bfloat16_as_ushort(hb) << 16) | __bfloat16_as_ushort(ha);
    lo = ((uint32_t)__bfloat16_as_ushort(lb) << 16) | __bfloat16_as_ushort(la);
}
/* fp16 split (GEMM activation planes) */
__device__ __forceinline__ void split2h(float a, float b, uint32_t& hi, uint32_t& lo) {
    __half ha = __float2half_rn(a), hb = __float2half_rn(b);
    __half la = __float2half_rn(a - __half2float(ha));
    __half lb = __float2half_rn(b - __half2float(hb));
    hi = ((uint32_t)__half_as_ushort(hb) << 16) | __half_as_ushort(ha);
    lo = ((uint32_t)__half_as_ushort(lb) << 16) | __half_as_ushort(la);
}
__device__ __forceinline__ uint32_t pack2h(float a, float b) {
    return ((uint32_t)__half_as_ushort(__float2half_rn(b)) << 16)
           | __half_as_ushort(__float2half_rn(a));
}

/* ---------------- preprocessing: fused split ---------------- */
#define SN0 (M_TOT*DIMC/4)
#define SN1 (3*DIMC*DIMC/4)
#define SN2 (DIMC*DIMC/4)

__global__ void split_all_kernel(const float* __restrict__ x,
                                 const float* __restrict__ wq,
                                 const float* __restrict__ wp) {
    int i = blockIdx.x * blockDim.x + threadIdx.x;
    int stride = gridDim.x * blockDim.x;
    const int total = SN0 + SN1 + SN2;
    for (; i < total; i += stride) {
        int j = i;
        if (j < SN0) {
            float4 v = ((const float4*)x)[j];
            uint32_t h0, l0, h1, l1;
            split2h(v.x, v.y, h0, l0);
            split2h(v.z, v.w, h1, l1);
            ((uint2*)g_xh)[j] = make_uint2(h0, h1);
            ((uint2*)g_xl)[j] = make_uint2(l0, l1);
        } else if (j < SN0 + SN1) {
            j -= SN0;
            float4 v = ((const float4*)wq)[j];
            ((uint2*)g_wqh)[j] = make_uint2(pack2h(v.x, v.y), pack2h(v.z, v.w));
        } else {
            j -= SN0 + SN1;
            float4 v = ((const float4*)wp)[j];
            ((uint2*)g_wph)[j] = make_uint2(pack2h(v.x, v.y), pack2h(v.z, v.w));
        }
    }
}

/* single block 1024 thr: sniff mask dtype, ballot-scan compact per batch */
__global__ void mask_prep_kernel(const unsigned char* __restrict__ m) {
    __shared__ int wsum[32];
    __shared__ int s_any;
    const int tid = threadIdx.x, lane = tid & 31, wid = tid >> 5;
    if (tid == 0) s_any = 0;
    __syncthreads();
    int loc = 0;
    for (int i = tid; i < BATCH*SEQ; i += 1024)
        if ((i & 3) && m[i]) loc = 1;
    if (loc) s_any = 1;
    __syncthreads();
    const bool mbyte = (s_any != 0);
    const int* mi = (const int*)m;
    for (int b = 0; b < BATCH; b++) {
        bool masked = mbyte ? (m[b*SEQ + tid] != 0) : (mi[b*SEQ + tid] != 0);
        unsigned bal = __ballot_sync(0xffffffffu, !masked);
        int rank = __popc(bal & ((1u << lane) - 1u));
        if (lane == 0) wsum[wid] = __popc(bal);
        __syncthreads();
        int off = 0, tot = 0;
#pragma unroll
        for (int w = 0; w < 32; w++) {
            int s = wsum[w];
            if (w < wid) off += s;
            tot += s;
        }
        if (!masked) g_kidx[b*SEQ + off + rank] = tid;
        if (tid >= tot) g_kidx[b*SEQ + tid] = 0;
        g_cmask[b*SEQ + tid] = (tid < tot) ? 0.f : -1e30f;
        if (tid == 0) g_kcnt[b] = tot;
        __syncthreads();
    }
}

/* ======================================================================
   fp16 2-pass warp-MMA NT GEMM: C = Ah.Bh + Al.Bh  (weight residual dropped).
   CTA 128x128, 8 warps (2x4), warp 64x32. KC=32, 2 stages, 3 planes/stage.
   MODE 0: QKV -> bf16 hi/lo q/k/v planes. MODE 1: proj -> fp32 out + bias.
   ====================================================================== */
#define KC2    32
#define NCH2   (768/KC2)          /* 24 */
#define GS     40                 /* halves per row (80 B) */
#define PLANE_B (128*GS*2)        /* 10240 B */
#define STAGE_B (3*PLANE_B)       /* 30720 B */
#define GEMM_SMEM (2*STAGE_B)     /* 61440 B */

template<int MODE>
__global__ void __launch_bounds__(256, 2) gemm_mma(
    const __half* __restrict__ Ahg, const __half* __restrict__ Alg,
    const __half* __restrict__ Bhg,
    const float* __restrict__ bias0, const float* __restrict__ bias1,
    float* __restrict__ Cout)
{
    extern __shared__ __align__(16) __half smb[];
    const uint32_t sb = smem_to_u32(smb);

    const int tid = threadIdx.x;
    const int lane = tid & 31;
    const int wid = tid >> 5;
    const int wm = wid >> 2, wn = wid & 3;
    const int bm = blockIdx.y * 128, bn = blockIdx.x * 128;

    const int a_row = lane & 15, a_cb = (lane >> 4) << 3;

    float acc[4][4][4];
#pragma unroll
    for (int i = 0; i < 4; i++)
#pragma unroll
        for (int j = 0; j < 4; j++)
#pragma unroll
            for (int t = 0; t < 4; t++) acc[i][j][t] = 0.f;

    /* one stage: 3 planes x 512 16B-slots -> 6 per thread */
    auto issue = [&](int kc) {
        const int k0 = kc * KC2;
        const uint32_t st = sb + (uint32_t)((kc & 1) * STAGE_B);
#pragma unroll
        for (int u = 0; u < 6; u++) {
            int idx = tid + u * 256;
            int plane = idx >> 9;            /* 0=Ah 1=Al 2=Bh */
            int rem = idx & 511;
            int row = rem >> 2;
            int c8 = (rem & 3) << 3;
            const __half* gp = (plane == 0) ? Ahg : (plane == 1) ? Alg : Bhg;
            int rb = (plane < 2) ? bm : bn;
            uint32_t d = st + (uint32_t)(plane * PLANE_B) + (uint32_t)((row * GS + c8) * 2);
            CP16(d, gp + (size_t)(rb + row) * 768 + k0 + c8);
        }
        CP_COMMIT();
    };

    issue(0);
    for (int kc = 0; kc < NCH2; kc++) {
        if (kc + 1 < NCH2) { issue(kc + 1); CP_WAIT1(); }
        else               { CP_WAIT0(); }
        __syncthreads();

        const uint32_t st = sb + (uint32_t)((kc & 1) * STAGE_B);
        const uint32_t pAh = st, pAl = st + PLANE_B, pBh = st + 2*PLANE_B;
#pragma unroll
        for (int ks = 0; ks < 2; ks++) {
            const int kh = ks * 16;
            uint32_t af[4][4], bfr[4][2];
#pragma unroll
            for (int mf = 0; mf < 4; mf++) {
                uint32_t ad = pAh + (uint32_t)(((wm*64 + mf*16 + a_row) * GS + kh + a_cb) * 2);
                ldsm_x4(af[mf][0], af[mf][1], af[mf][2], af[mf][3], ad);
            }
#pragma unroll
            for (int np = 0; np < 2; np++) {
                uint32_t bd = pBh + (uint32_t)(((wn*32 + np*16 + a_row) * GS + kh + a_cb) * 2);
                uint32_t r0, r1, r2, r3;
                ldsm_x4(r0, r1, r2, r3, bd);
                bfr[2*np][0] = r0; bfr[2*np][1] = r2;
                bfr[2*np+1][0] = r1; bfr[2*np+1][1] = r3;
            }
            /* pass 1: Ah.Bh */
#pragma unroll
            for (int mf = 0; mf < 4; mf++)
#pragma unroll
                for (int nf = 0; nf < 4; nf++)
                    mma_f16(acc[mf][nf], af[mf], bfr[nf]);
            /* pass 2: Al.Bh (reuse af regs) */
#pragma unroll
            for (int mf = 0; mf < 4; mf++) {
                uint32_t ad = pAl + (uint32_t)(((wm*64 + mf*16 + a_row) * GS + kh + a_cb) * 2);
                ldsm_x4(af[mf][0], af[mf][1], af[mf][2], af[mf][3], ad);
            }
#pragma unroll
            for (int mf = 0; mf < 4; mf++)
#pragma unroll
                for (int nf = 0; nf < 4; nf++)
                    mma_f16(acc[mf][nf], af[mf], bfr[nf]);
        }
        __syncthreads();
    }

    const int gr = lane >> 2;
    const int gc = (lane & 3) << 1;
#pragma unroll
    for (int mf = 0; mf < 4; mf++) {
#pragma unroll
        for (int nf = 0; nf < 4; nf++) {
            int n0 = bn + wn*32 + nf*8 + gc;
#pragma unroll
            for (int half = 0; half < 2; half++) {
                int m = bm + wm*64 + mf*16 + gr + half*8;
                float v0 = acc[mf][nf][half*2 + 0];
                float v1 = acc[mf][nf][half*2 + 1];
                if (MODE == 1) {
                    float2 o = make_float2(v0 + bias0[n0], v1 + bias0[n0+1]);
                    *(float2*)(Cout + (size_t)m * 768 + n0) = o;
                } else {
                    int which = n0 / 768;
                    int nn = n0 % 768;
                    int h = nn >> 6, d0 = nn & 63;
                    int b = m >> 10, tok = m & 1023;
                    if (which == 0) {
                        v0 = (v0 + bias0[nn])   * QK_SCALE;
                        v1 = (v1 + bias0[nn+1]) * QK_SCALE;
                    } else if (which == 2) {
                        v0 += bias1[nn];
                        v1 += bias1[nn+1];
                    }
                    uint32_t hp, lp;
                    split2(v0, v1, hp, lp);
                    size_t off = ((size_t)((b*NH + h)*SEQ + tok)) * HD + d0;
                    bf16* ph = (which == 0) ? g_qh : ((which == 1) ? g_kh : g_vh);
                    bf16* pl = (which == 0) ? g_ql : ((which == 1) ? g_kl : g_vl);
                    *(uint32_t*)(ph + off) = hp;
                    *(uint32_t*)(pl + off) = lp;
                }
            }
        }
    }
}

/* ======================================================================
   flash attention over compacted keys (bf16 3-pass, proven R13 version).
   Epilogue writes fp16 hi/lo planes for the proj GEMM.
   ====================================================================== */
#define FS     72
#define FPLANE_B (64*FS*2)
#define FSTAGE_B (4*FPLANE_B)
#define FLASH_SMEM (2*FSTAGE_B)

__global__ void __launch_bounds__(128, 3) flash_mma()
{
    extern __shared__ __align__(16) bf16 fsm[];
    const uint32_t sb = smem_to_u32(fsm);

    const int tid = threadIdx.x;
    const int lane = tid & 31;
    const int wid = tid >> 5;
    const int bh = blockIdx.y;
    const int qt = blockIdx.x;
    const int b = bh / NH, h = bh % NH;

    const size_t qbase = ((size_t)bh*SEQ + qt*64) * HD;
    const size_t kvbase = (size_t)bh*SEQ*HD;
    const int cnt = g_kcnt[b];
    const int ntiles = (cnt + 63) >> 6;
    const int* kidx = g_kidx + b*SEQ;

#pragma unroll
    for (int u = 0; u < 8; u++) {
        int idx = tid + u * 128;
        int plane = idx >> 9;
        int rem = idx & 511;
        int row = rem >> 3;
        int c8 = (rem & 7) << 3;
        const bf16* src = plane ? g_ql : g_qh;
        *(uint4*)(fsm + plane*(64*FS) + row*FS + c8) =
            *(const uint4*)(src + qbase + (size_t)row*64 + c8);
    }
    __syncthreads();

    uint32_t qh[4][4], ql[4][4];
    {
        int row = wid*16 + (lane & 15);
        int cb = (lane >> 4) << 3;
#pragma unroll
        for (int ks = 0; ks < 4; ks++) {
            uint32_t off = (uint32_t)((row*FS + ks*16 + cb) * 2);
            ldsm_x4(qh[ks][0], qh[ks][1], qh[ks][2], qh[ks][3], sb + off);
            ldsm_x4(ql[ks][0], ql[ks][1], ql[ks][2], ql[ks][3],
                    sb + (uint32_t)FPLANE_B + off);
        }
    }
    __syncthreads();

    auto issue_kv = [&](int j) {
        const uint32_t st = sb + (uint32_t)((j & 1) * FSTAGE_B);
#pragma unroll
        for (int u = 0; u < 16; u++) {
            int idx = tid + u * 128;
            int plane = idx >> 9;
            int rem = idx & 511;
            int row = rem >> 3;
            int c8 = (rem & 7) << 3;
            int src_row = kidx[j*64 + row];
            const bf16* gp = (plane == 0) ? g_kh : (plane == 1) ? g_kl
                             : (plane == 2) ? g_vh : g_vl;
            uint32_t d = st + (uint32_t)(plane * FPLANE_B) + (uint32_t)((row*FS + c8) * 2);
            CP16(d, gp + kvbase + (size_t)src_row*64 + c8);
        }
        CP_COMMIT();
    };

    float o[8][4];
#pragma unroll
    for (int i = 0; i < 8; i++)
#pragma unroll
        for (int t = 0; t < 4; t++) o[i][t] = 0.f;
    float m0 = -1e30f, m1 = -1e30f, l0 = 0.f, l1 = 0.f;

    const int gr = lane >> 2;
    const int gc = (lane & 3) << 1;
    const int frow = lane & 15;
    const int fcb = (lane >> 4) << 3;

    issue_kv(0);
    for (int kt = 0; kt < ntiles; kt++) {
        float2 mk[8];
#pragma unroll
        for (int nf = 0; nf < 8; nf++)
            mk[nf] = *(const float2*)(g_cmask + b*SEQ + kt*64 + nf*8 + gc);

        if (kt + 1 < ntiles) { issue_kv(kt + 1); CP_WAIT1(); }
        else                 { CP_WAIT0(); }
        __syncthreads();

        const uint32_t st = sb + (uint32_t)((kt & 1) * FSTAGE_B);
        const uint32_t pKh = st, pKl = st + FPLANE_B;
        const uint32_t pVh = st + 2*FPLANE_B, pVl = st + 3*FPLANE_B;

        float s4[8][4];
#pragma unroll
        for (int i = 0; i < 8; i++)
#pragma unroll
            for (int t = 0; t < 4; t++) s4[i][t] = 0.f;

#pragma unroll
        for (int ks = 0; ks < 4; ks++) {
            uint32_t kbh[8][2], kbl[8][2];
#pragma unroll
            for (int np = 0; np < 4; np++) {
                uint32_t off = (uint32_t)(((np*16 + frow)*FS + ks*16 + fcb) * 2);
                uint32_t r0, r1, r2, r3;
                ldsm_x4(r0, r1, r2, r3, pKh + off);
                kbh[2*np][0] = r0; kbh[2*np][1] = r2;
                kbh[2*np+1][0] = r1; kbh[2*np+1][1] = r3;
                ldsm_x4(r0, r1, r2, r3, pKl + off);
                kbl[2*np][0] = r0; kbl[2*np][1] = r2;
                kbl[2*np+1][0] = r1; kbl[2*np+1][1] = r3;
            }
#pragma unroll
            for (int nf = 0; nf < 8; nf++) mma_bf16(s4[nf], qh[ks], kbh[nf]);
#pragma unroll
            for (int nf = 0; nf < 8; nf++) mma_bf16(s4[nf], ql[ks], kbh[nf]);
#pragma unroll
            for (int nf = 0; nf < 8; nf++) mma_bf16(s4[nf], qh[ks], kbl[nf]);
        }

        float tm0 = -1e30f, tm1 = -1e30f;
#pragma unroll
        for (int nf = 0; nf < 8; nf++) {
            s4[nf][0] += mk[nf].x; s4[nf][1] += mk[nf].y;
            s4[nf][2] += mk[nf].x; s4[nf][3] += mk[nf].y;
            tm0 = fmaxf(tm0, fmaxf(s4[nf][0], s4[nf][1]));
            tm1 = fmaxf(tm1, fmaxf(s4[nf][2], s4[nf][3]));
        }
        tm0 = fmaxf(tm0, __shfl_xor_sync(0xffffffffu, tm0, 1));
        tm0 = fmaxf(tm0, __shfl_xor_sync(0xffffffffu, tm0, 2));
        tm1 = fmaxf(tm1, __shfl_xor_sync(0xffffffffu, tm1, 1));
        tm1 = fmaxf(tm1, __shfl_xor_sync(0xffffffffu, tm1, 2));
        float mn0 = fmaxf(m0, tm0), mn1 = fmaxf(m1, tm1);
        float al0 = __expf(m0 - mn0), al1 = __expf(m1 - mn1);
        m0 = mn0; m1 = mn1;
        float ls0 = 0.f, ls1 = 0.f;
#pragma unroll
        for (int nf = 0; nf < 8; nf++) {
            s4[nf][0] = __expf(s4[nf][0] - mn0);
            s4[nf][1] = __expf(s4[nf][1] - mn0);
            s4[nf][2] = __expf(s4[nf][2] - mn1);
            s4[nf][3] = __expf(s4[nf][3] - mn1);
            ls0 += s4[nf][0] + s4[nf][1];
            ls1 += s4[nf][2] + s4[nf][3];
        }
        ls0 += __shfl_xor_sync(0xffffffffu, ls0, 1);
        ls0 += __shfl_xor_sync(0xffffffffu, ls0, 2);
        ls1 += __shfl_xor_sync(0xffffffffu, ls1, 1);
        ls1 += __shfl_xor_sync(0xffffffffu, ls1, 2);
        l0 = l0 * al0 + ls0;
        l1 = l1 * al1 + ls1;
#pragma unroll
        for (int nf = 0; nf < 8; nf++) {
            o[nf][0] *= al0; o[nf][1] *= al0;
            o[nf][2] *= al1; o[nf][3] *= al1;
        }

#pragma unroll
        for (int ksv = 0; ksv < 4; ksv++) {
            uint32_t ph[4], pl[4];
            split2(s4[2*ksv][0],   s4[2*ksv][1],   ph[0], pl[0]);
            split2(s4[2*ksv][2],   s4[2*ksv][3],   ph[1], pl[1]);
            split2(s4[2*ksv+1][0], s4[2*ksv+1][1], ph[2], pl[2]);
            split2(s4[2*ksv+1][2], s4[2*ksv+1][3], ph[3], pl[3]);
            uint32_t vhf[8][2], vlf[8][2];
#pragma unroll
            for (int np = 0; np < 4; np++) {
                uint32_t off = (uint32_t)(((ksv*16 + frow)*FS + np*16 + fcb) * 2);
                uint32_t r0, r1, r2, r3;
                ldsm_x4_t(r0, r1, r2, r3, pVh + off);
                vhf[2*np][0] = r0; vhf[2*np][1] = r1;
                vhf[2*np+1][0] = r2; vhf[2*np+1][1] = r3;
                ldsm_x4_t(r0, r1, r2, r3, pVl + off);
                vlf[2*np][0] = r0; vlf[2*np][1] = r1;
                vlf[2*np+1][0] = r2; vlf[2*np+1][1] = r3;
            }
#pragma unroll
            for (int nf = 0; nf < 8; nf++) mma_bf16(o[nf], ph, vhf[nf]);
#pragma unroll
            for (int nf = 0; nf < 8; nf++) mma_bf16(o[nf], ph, vlf[nf]);
#pragma unroll
            for (int nf = 0; nf < 8; nf++) mma_bf16(o[nf], pl, vhf[nf]);
        }
        __syncthreads();
    }

    /* ---- finalize: write fp16 hi/lo planes for proj ---- */
    float inv0 = 1.f / l0, inv1 = 1.f / l1;
    int tok0 = qt*64 + wid*16 + gr;
    size_t r0g = ((size_t)(b*SEQ + tok0)) * DIMC + h*HD;
    size_t r1g = r0g + 8*DIMC;
#pragma unroll
    for (int nf = 0; nf < 8; nf++) {
        int d = nf*8 + gc;
        uint32_t hp, lp;
        split2h(o[nf][0]*inv0, o[nf][1]*inv0, hp, lp);
        *(uint32_t*)(g_aoh + r0g + d) = hp;
        *(uint32_t*)(g_aol + r0g + d) = lp;
        split2h(o[nf][2]*inv1, o[nf][3]*inv1, hp, lp);
        *(uint32_t*)(g_aoh + r1g + d) = hp;
        *(uint32_t*)(g_aol + r1g + d) = lp;
    }
}

/* ---------------- launcher ---------------- */
extern "C" void kernel_launch(void* const* d_in, const int* in_sizes, int n_in,
                              void* d_out, int out_size)
{
    const float* x           = (const float*)d_in[0];
    const unsigned char* msk = (const unsigned char*)d_in[1];
    const float* qkv_w       = (const float*)d_in[2];
    const float* q_bias      = (const float*)d_in[3];
    const float* v_bias      = (const float*)d_in[4];
    const float* proj_w      = (const float*)d_in[5];
    const float* proj_b      = (const float*)d_in[6];
    float* out               = (float*)d_out;

    (void)in_sizes; (void)n_in; (void)out_size;

    cudaFuncSetAttribute(gemm_mma<0>, cudaFuncAttributeMaxDynamicSharedMemorySize, GEMM_SMEM);
    cudaFuncSetAttribute(gemm_mma<1>, cudaFuncAttributeMaxDynamicSharedMemorySize, GEMM_SMEM);
    cudaFuncSetAttribute(flash_mma, cudaFuncAttributeMaxDynamicSharedMemorySize, FLASH_SMEM);

    mask_prep_kernel<<<1, 1024>>>(msk);
    split_all_kernel<<<2048, 256>>>(x, qkv_w, proj_w);

    __half *xh, *xl, *wqh, *wph, *aoh, *aol;
    cudaGetSymbolAddress((void**)&xh,  g_xh);  cudaGetSymbolAddress((void**)&xl,  g_xl);
    cudaGetSymbolAddress((void**)&wqh, g_wqh); cudaGetSymbolAddress((void**)&wph, g_wph);
    cudaGetSymbolAddress((void**)&aoh, g_aoh); cudaGetSymbolAddress((void**)&aol, g_aol);

    gemm_mma<0><<<dim3(2304/128, M_TOT/128), 256, GEMM_SMEM>>>(
        xh, xl, wqh, q_bias, v_bias, nullptr);

    flash_mma<<<dim3(SEQ/64, BH), 128, FLASH_SMEM>>>();

    gemm_mma<1><<<dim3(768/128, M_TOT/128), 256, GEMM_SMEM>>>(
        aoh, aol, wph, proj_b, nullptr, out);
}